// round 14
// baseline (speedup 1.0000x reference)
#include <cuda_runtime.h>
#include <cuda_fp16.h>
#include <cstdint>

// Problem: x [B=8, C=512, L=2048], GroupNorm(32) -> QKV -> attention -> O-proj + residual.
// Algebra: out = Pn @ (h @ (Wo·Wv)^T) + (Wo·bv + bo) + x   (softmax rows sum to 1)
#define BDIM 8
#define CDIM 512
#define LDIM 2048
#define NGRP 32
#define CPG  (CDIM / NGRP)   // 16
#define GN_EPS 1e-5f
#define EXP_SHIFT 4.0f

#define CL 1048576LL   // C*L per-batch elems
#define LL 4194304LL   // L*L per-batch elems

// Scratch (bytes):
//  ht   [B,L,C] fp16 @ 0
//  qh   [B,L,C] fp16 @ 16777216
//  kh   [B,L,C] fp16 @ 33554432
//  uTh  [B,C,L] fp16 @ 50331648
//  rsum [B,L]  fp32 @ 67108864
//  b2   [C]    fp32 @ 67174400
//  p    [B,L,L] fp16 @ 83886080
//  wh   [3C,C] fp16 @ 150994944      (wq | wk | W2)
__device__ __align__(256) unsigned char g_scratch[152567808];

// ---------------------------------------------------------------------------
__device__ __forceinline__ float warp_sum(float v) {
#pragma unroll
    for (int o = 16; o > 0; o >>= 1) v += __shfl_xor_sync(0xFFFFFFFFu, v, o);
    return v;
}
__device__ __forceinline__ void mma_f16(float* c, const uint32_t* a, const uint32_t* b) {
    asm volatile(
        "mma.sync.aligned.m16n8k16.row.col.f32.f16.f16.f32 "
        "{%0,%1,%2,%3}, {%4,%5,%6,%7}, {%8,%9}, {%0,%1,%2,%3};"
        : "+f"(c[0]), "+f"(c[1]), "+f"(c[2]), "+f"(c[3])
        : "r"(a[0]), "r"(a[1]), "r"(a[2]), "r"(a[3]), "r"(b[0]), "r"(b[1]));
}
__device__ __forceinline__ void ldsm_x4(uint32_t& r0, uint32_t& r1, uint32_t& r2,
                                        uint32_t& r3, uint32_t addr) {
    asm volatile("ldmatrix.sync.aligned.m8n8.x4.shared.b16 {%0,%1,%2,%3}, [%4];"
                 : "=r"(r0), "=r"(r1), "=r"(r2), "=r"(r3) : "r"(addr));
}
__device__ __forceinline__ void cp_async16(uint32_t dst, const void* src) {
    asm volatile("cp.async.cg.shared.global [%0], [%1], 16;" :: "r"(dst), "l"(src));
}
__device__ __forceinline__ void cp_commit() {
    asm volatile("cp.async.commit_group;" ::: "memory");
}
template<int N>
__device__ __forceinline__ void cp_wait() {
    asm volatile("cp.async.wait_group %0;" :: "n"(N) : "memory");
}

// ============================================================================
// Prologue (one launch, all-independent pieces):
//  blocks [0,256)      : GroupNorm + transpose  x -> ht [B,L,C] fp16
//  blocks [256,2304)   : convert wq -> wh slot0, wk -> wh slot1; zero rsum
//  blocks [2304,2368)  : b2[o] = wo[o,:]·bv + bo[o]
//  blocks [2368,2624)  : W2 = Wo @ Wv in fp32 (32x32 tiles) -> wh slot2 (fp16)
// ============================================================================
__global__ __launch_bounds__(256)
void prep_kernel(const float* __restrict__ x, const float* __restrict__ gamma,
                 const float* __restrict__ beta, __half* __restrict__ ht,
                 const float* __restrict__ wq, const float* __restrict__ wk,
                 const float* __restrict__ wv, const float* __restrict__ wo,
                 const float* __restrict__ bv, const float* __restrict__ bo,
                 __half* __restrict__ wh, float* __restrict__ rsum,
                 float* __restrict__ b2) {
    __shared__ float sh1[8], sh2[8];
    __shared__ float scg[CPG], sbg[CPG];
    __shared__ float tile[CPG][133];
    __shared__ float woS[32][65];
    __shared__ float wvS[64][33];

    const int bid = blockIdx.x;
    const int tid = threadIdx.x;

    if (bid < 256) {
        // ---------------- GroupNorm + transpose ----------------
        const int b = bid / NGRP;
        const int g = bid % NGRP;
        const size_t base = ((size_t)b * CDIM + (size_t)g * CPG) * LDIM;
        const float4* xp = reinterpret_cast<const float4*>(x + base);

        const int n4 = CPG * LDIM / 4;  // 8192
        float s = 0.f, ss = 0.f;
        for (int i = tid; i < n4; i += 256) {
            float4 t = xp[i];
            s  += t.x + t.y + t.z + t.w;
            ss += t.x * t.x + t.y * t.y + t.z * t.z + t.w * t.w;
        }
        int lane = tid & 31, wid = tid >> 5;
        s = warp_sum(s); ss = warp_sum(ss);
        if (lane == 0) { sh1[wid] = s; sh2[wid] = ss; }
        __syncthreads();
        if (wid == 0) {
            s  = (lane < 8) ? sh1[lane] : 0.f;
            ss = (lane < 8) ? sh2[lane] : 0.f;
            s = warp_sum(s); ss = warp_sum(ss);
            if (lane == 0) { sh1[0] = s; sh2[0] = ss; }
        }
        __syncthreads();
        const float inv_n = 1.f / (float)(CPG * LDIM);
        const float mean = sh1[0] * inv_n;
        const float var  = sh2[0] * inv_n - mean * mean;
        const float rstd = rsqrtf(var + GN_EPS);
        if (tid < CPG) {
            float sc = gamma[g * CPG + tid] * rstd;
            scg[tid] = sc;
            sbg[tid] = beta[g * CPG + tid] - mean * sc;
        }
        __syncthreads();

        for (int l0 = 0; l0 < LDIM; l0 += 128) {
            for (int it = tid; it < 512; it += 256) {
                int c  = it >> 5;
                int l4 = (it & 31) * 4;
                float4 t = *reinterpret_cast<const float4*>(
                    &x[base + (size_t)c * LDIM + l0 + l4]);
                float sc = scg[c], sb = sbg[c];
                tile[c][l4 + 0] = t.x * sc + sb;
                tile[c][l4 + 1] = t.y * sc + sb;
                tile[c][l4 + 2] = t.z * sc + sb;
                tile[c][l4 + 3] = t.w * sc + sb;
            }
            __syncthreads();
            for (int it = tid; it < 512; it += 256) {
                int l  = it >> 2;
                int c4 = (it & 3) * 4;
                __half2* dst = reinterpret_cast<__half2*>(
                    ht + ((size_t)b * LDIM + l0 + l) * CDIM + g * CPG + c4);
                dst[0] = __floats2half2_rn(tile[c4 + 0][l], tile[c4 + 1][l]);
                dst[1] = __floats2half2_rn(tile[c4 + 2][l], tile[c4 + 3][l]);
            }
            __syncthreads();
        }
    } else if (bid < 2304) {
        // ---------------- convert wq, wk; zero rsum ----------------
        int i = (bid - 256) * 256 + tid;           // 0 .. 524287
        int which = i >> 18;                       // 0=wq, 1=wk
        int off = i & 0x3FFFF;
        wh[which * 262144 + off] = __float2half(which == 0 ? wq[off] : wk[off]);
        if (i < BDIM * LDIM) rsum[i] = 0.f;
    } else if (bid < 2368) {
        // ---------------- b2 = Wo @ bv + bo ----------------
        const int o = (bid - 2304) * 8 + (tid >> 5);
        const int lane = tid & 31;
        float s = 0.f;
        for (int c = lane; c < CDIM; c += 32) s += wo[o * CDIM + c] * bv[c];
        s = warp_sum(s);
        if (lane == 0) b2[o] = s + bo[o];
    } else {
        // ---------------- W2 = Wo @ Wv (fp32) -> wh slot2 fp16 ----------------
        const int bidx = bid - 2368;               // 0..255
        const int mo = (bidx >> 4) * 32;           // Wo row block
        const int eo = (bidx & 15) * 32;           // Wv col block
        const int tr = (tid >> 4) * 2;
        const int tc = (tid & 15) * 2;
        float a00 = 0.f, a01 = 0.f, a10 = 0.f, a11 = 0.f;

        for (int k0 = 0; k0 < CDIM; k0 += 64) {
#pragma unroll
            for (int t = 0; t < 8; t++) {
                int idx = tid + t * 256;
                int r = idx >> 6, c = idx & 63;
                woS[r][c] = wo[(mo + r) * CDIM + k0 + c];
                int r2 = idx >> 5, c2 = idx & 31;
                wvS[r2][c2] = wv[(k0 + r2) * CDIM + eo + c2];
            }
            __syncthreads();
#pragma unroll 8
            for (int k = 0; k < 64; k++) {
                float w0 = woS[tr][k], w1 = woS[tr + 1][k];
                float v0 = wvS[k][tc], v1 = wvS[k][tc + 1];
                a00 += w0 * v0; a01 += w0 * v1;
                a10 += w1 * v0; a11 += w1 * v1;
            }
            __syncthreads();
        }
        __half* w2 = wh + 524288;
        *reinterpret_cast<__half2*>(&w2[(mo + tr) * CDIM + eo + tc]) =
            __floats2half2_rn(a00, a01);
        *reinterpret_cast<__half2*>(&w2[(mo + tr + 1) * CDIM + eo + tc]) =
            __floats2half2_rn(a10, a11);
    }
}

// ============================================================================
// fp16 tensor-core GEMM: D[m,n] = sum_k A[m,k]*B[n,k]  (A:[M,K], B:[N,K] fp16)
// CTA: 128 thr (4 warps), 128x128 tile, warp tile 64x64 (2x2 warp grid).
// K-chunk 64 halves, NS-stage cp.async (NS=2 or 3), XOR swizzle, ldmatrix.
// MB = min blocks per SM (launch bounds).
// EPI: 5 = merged QKU routing (q/k row-major + bias, u transposed no bias)
//      6 = scores: P = fp16(exp(c*alpha - EXP_SHIFT)), atomic row sums -> rsum
//      8 = final: fp32 out = c/rsum[n] + bias[m] + resid[m*ldc+n]
// ============================================================================
#define STAGE_BYTES 32768

template<int EPI, int MB, int NS>
__global__ __launch_bounds__(128, MB)
void gemm_h(const __half* __restrict__ A, const __half* __restrict__ B,
            void* __restrict__ Dv, int K, int lda, int ldb, int ldc,
            long long sA, long long sB, long long sD,
            const float* __restrict__ bias, float alpha,
            const float* __restrict__ resid, float* __restrict__ rsum,
            void* __restrict__ Dv2, void* __restrict__ Dv3,
            const float* __restrict__ bias2) {
    extern __shared__ char smem[];
    const uint32_t sb = (uint32_t)__cvta_generic_to_shared(smem);
    const int tid = threadIdx.x;
    const int lane = tid & 31;
    const int warp = tid >> 5;
    const int gid = lane >> 2;
    const int tig = lane & 3;
    const int wm = warp & 1;
    const int wn = warp >> 1;
    const int m0 = blockIdx.y * 128;
    const int n0 = blockIdx.x * 128;
    const int bz = blockIdx.z;

    A += (long long)bz * sA;
    B += (long long)bz * sB;

    const int lm = tid >> 3;
    const int lg = tid & 7;
    const __half* Ap = A + (long long)(m0 + lm) * lda + lg * 8;
    const __half* Bp = B + (long long)(n0 + lm) * ldb + lg * 8;
    const uint32_t sts_off = (uint32_t)(lm * 128 + (((lg ^ lm) & 7) << 4));

    const int r7 = lane & 7;
    const int lhi = lane >> 4;
    const int arow = ((lane >> 3) & 1) * 8 + r7;
    const int bhi = (lane >> 3) & 1;
    const int brow = ((lane >> 4) & 1) * 8 + r7;
    uint32_t aRowOff[4], bRowOff[4];
#pragma unroll
    for (int mt = 0; mt < 4; mt++)
        aRowOff[mt] = (uint32_t)((wm * 64 + mt * 16 + arow) * 128);
#pragma unroll
    for (int j = 0; j < 4; j++)
        bRowOff[j] = (uint32_t)((wn * 64 + j * 16 + brow) * 128) + 16384u;

    const int nch = K / 64;

#define ISSUE_STAGE(st, buf) do {                                             \
        const uint32_t d0 = sb + (uint32_t)(buf) * STAGE_BYTES + sts_off;     \
        const __half* ap = Ap + (st) * 64;                                    \
        const __half* bp = Bp + (st) * 64;                                    \
        _Pragma("unroll")                                                     \
        for (int u = 0; u < 8; u++)                                           \
            cp_async16(d0 + u * 2048, ap + (long long)u * 16 * lda);          \
        _Pragma("unroll")                                                     \
        for (int u = 0; u < 8; u++)                                           \
            cp_async16(d0 + 16384 + u * 2048, bp + (long long)u * 16 * ldb);  \
    } while (0)

    ISSUE_STAGE(0, 0); cp_commit();
    ISSUE_STAGE(1, 1); cp_commit();

    float acc[4][8][4];
#pragma unroll
    for (int i = 0; i < 4; i++)
#pragma unroll
        for (int j = 0; j < 8; j++)
#pragma unroll
            for (int r = 0; r < 4; r++) acc[i][j][r] = 0.f;

    for (int i = 0; i < nch; i++) {
        cp_wait<1>();
        __syncthreads();
        if (NS == 3) {
            if (i + 2 < nch) ISSUE_STAGE(i + 2, (i + 2) % 3);
            cp_commit();
        }

        const uint32_t stage = sb + (uint32_t)(i % NS) * STAGE_BYTES;
#pragma unroll
        for (int ks = 0; ks < 4; ks++) {
            // B fragments first (16 regs), then stream A per m-tile (4 regs live)
            const uint32_t swb = (uint32_t)((((2 * ks + bhi) ^ r7) & 7) << 4);
            uint32_t bfr[8][2];
#pragma unroll
            for (int j = 0; j < 4; j++)
                ldsm_x4(bfr[2 * j][0], bfr[2 * j][1], bfr[2 * j + 1][0],
                        bfr[2 * j + 1][1], stage + bRowOff[j] + swb);
            const uint32_t swa = (uint32_t)((((2 * ks + lhi) ^ r7) & 7) << 4);
#pragma unroll
            for (int mt = 0; mt < 4; mt++) {
                uint32_t afr[4];
                ldsm_x4(afr[0], afr[1], afr[2], afr[3],
                        stage + aRowOff[mt] + swa);
#pragma unroll
                for (int nt = 0; nt < 8; nt++)
                    mma_f16(acc[mt][nt], afr, bfr[nt]);
            }
        }

        if (NS == 2) {
            __syncthreads();
            if (i + 2 < nch) ISSUE_STAGE(i + 2, i & 1);
            cp_commit();
        }
    }
#undef ISSUE_STAGE

    // EPI 8: per-column inverse attention row-sums (n indexes the L axis)
    float invn[8][2];
    if (EPI == 8) {
#pragma unroll
        for (int nt = 0; nt < 8; nt++) {
            const int n = n0 + wn * 64 + nt * 8 + tig * 2;
            invn[nt][0] = 1.f / rsum[(long long)bz * LDIM + n];
            invn[nt][1] = 1.f / rsum[(long long)bz * LDIM + n + 1];
        }
    }

#pragma unroll
    for (int mt = 0; mt < 4; mt++) {
        const int m = m0 + wm * 64 + mt * 16 + gid;
        float rs0 = 0.f, rs1 = 0.f;
#pragma unroll
        for (int nt = 0; nt < 8; nt++) {
            const int n = n0 + wn * 64 + nt * 8 + tig * 2;
            float* c = acc[mt][nt];
            if (EPI == 5) {
                const int which = n >> 9;          // 0=q, 1=k, 2=u
                const int nl = n & 511;
                if (which < 2) {
                    __half* Dh = ((which == 0) ? (__half*)Dv : (__half*)Dv2)
                                 + (long long)bz * CL;
                    const float* bb = (which == 0) ? bias : bias2;
                    const float b0v = bb[nl], b1v = bb[nl + 1];
                    *reinterpret_cast<__half2*>(Dh + (long long)m * CDIM + nl) =
                        __floats2half2_rn(c[0] + b0v, c[1] + b1v);
                    *reinterpret_cast<__half2*>(Dh + (long long)(m + 8) * CDIM + nl) =
                        __floats2half2_rn(c[2] + b0v, c[3] + b1v);
                } else {
                    __half* Dh = (__half*)Dv3 + (long long)bz * CL;
                    Dh[(long long)nl * LDIM + m]           = __float2half(c[0]);
                    Dh[(long long)(nl + 1) * LDIM + m]     = __float2half(c[1]);
                    Dh[(long long)nl * LDIM + m + 8]       = __float2half(c[2]);
                    Dh[(long long)(nl + 1) * LDIM + m + 8] = __float2half(c[3]);
                }
            } else if (EPI == 6) {
                __half* Dh = (__half*)Dv + (long long)bz * sD;
                const float e0 = __expf(c[0] * alpha - EXP_SHIFT);
                const float e1 = __expf(c[1] * alpha - EXP_SHIFT);
                const float e2 = __expf(c[2] * alpha - EXP_SHIFT);
                const float e3 = __expf(c[3] * alpha - EXP_SHIFT);
                *reinterpret_cast<__half2*>(Dh + (long long)m * ldc + n) =
                    __floats2half2_rn(e0, e1);
                *reinterpret_cast<__half2*>(Dh + (long long)(m + 8) * ldc + n) =
                    __floats2half2_rn(e2, e3);
                rs0 += e0 + e1;
                rs1 += e2 + e3;
            } else {  // EPI == 8
                float* Df = (float*)Dv + (long long)bz * sD;
                const float* rs = resid + (long long)bz * sD;
                const float bm0 = bias[m], bm1 = bias[m + 8];
                const float2 r0 = *reinterpret_cast<const float2*>(
                    &rs[(long long)m * ldc + n]);
                const float2 r1 = *reinterpret_cast<const float2*>(
                    &rs[(long long)(m + 8) * ldc + n]);
                *reinterpret_cast<float2*>(&Df[(long long)m * ldc + n]) =
                    make_float2(c[0] * invn[nt][0] + bm0 + r0.x,
                                c[1] * invn[nt][1] + bm0 + r0.y);
                *reinterpret_cast<float2*>(&Df[(long long)(m + 8) * ldc + n]) =
                    make_float2(c[2] * invn[nt][0] + bm1 + r1.x,
                                c[3] * invn[nt][1] + bm1 + r1.y);
            }
        }
        if (EPI == 6) {
            rs0 += __shfl_xor_sync(0xFFFFFFFFu, rs0, 1);
            rs0 += __shfl_xor_sync(0xFFFFFFFFu, rs0, 2);
            rs1 += __shfl_xor_sync(0xFFFFFFFFu, rs1, 1);
            rs1 += __shfl_xor_sync(0xFFFFFFFFu, rs1, 2);
            if (tig == 0) {
                atomicAdd(&rsum[(long long)bz * LDIM + m], rs0);
                atomicAdd(&rsum[(long long)bz * LDIM + m + 8], rs1);
            }
        }
    }
}

// ============================================================================
// Launch
// ============================================================================
extern "C" void kernel_launch(void* const* d_in, const int* in_sizes, int n_in,
                              void* d_out, int out_size) {
    (void)in_sizes; (void)n_in; (void)out_size;
    const float* x   = (const float*)d_in[0];
    const float* gns = (const float*)d_in[1];
    const float* gnb = (const float*)d_in[2];
    const float* wq  = (const float*)d_in[3];
    const float* bq  = (const float*)d_in[4];
    const float* wk  = (const float*)d_in[5];
    const float* bk  = (const float*)d_in[6];
    const float* wv  = (const float*)d_in[7];
    const float* bv  = (const float*)d_in[8];
    const float* wo  = (const float*)d_in[9];
    const float* bo  = (const float*)d_in[10];
    float* out = (float*)d_out;

    unsigned char* base = nullptr;
    cudaGetSymbolAddress((void**)&base, g_scratch);
    __half* ht   = (__half*)(base);
    __half* qh   = (__half*)(base + 16777216);
    __half* kh   = (__half*)(base + 33554432);
    __half* uTh  = (__half*)(base + 50331648);
    float*  rsum = (float*)(base + 67108864);
    float*  b2   = (float*)(base + 67174400);
    __half* p    = (__half*)(base + 83886080);
    __half* wh   = (__half*)(base + 150994944);   // [wq | wk | W2]

    const float attn_scale = 0.044194173824159216f;  // 512^-0.5

    static bool attr_done = false;
    if (!attr_done) {
        cudaFuncSetAttribute((const void*)gemm_h<5, 2, 3>,
                             cudaFuncAttributeMaxDynamicSharedMemorySize, 3 * STAGE_BYTES);
        cudaFuncSetAttribute((const void*)gemm_h<6, 3, 2>,
                             cudaFuncAttributeMaxDynamicSharedMemorySize, 2 * STAGE_BYTES);
        cudaFuncSetAttribute((const void*)gemm_h<8, 3, 2>,
                             cudaFuncAttributeMaxDynamicSharedMemorySize, 2 * STAGE_BYTES);
        attr_done = true;
    }

    // 0) Prologue: gn+transpose | wq/wk convert + rsum | b2 | W2 (fp32) — one launch
    prep_kernel<<<2624, 256>>>(x, gns, gnb, ht, wq, wk, wv, wo, bv, bo,
                               wh, rsum, b2);

    // 1) Merged QKU projection: M=L, N=3C=1536, K=C
    {
        dim3 grid(1536 / 128, LDIM / 128, BDIM);
        gemm_h<5, 2, 3><<<grid, 128, 3 * STAGE_BYTES>>>(ht, wh, qh,
            CDIM, CDIM, CDIM, CDIM, CL, 0, CL, bq, 0.f, nullptr, nullptr,
            kh, uTh, bk);
    }

    // 2) Scores fused with exp: p[i,j] = fp16(exp(scale*q.k - 4)), rsum[i] += ...
    {
        dim3 grid(LDIM / 128, LDIM / 128, BDIM);
        gemm_h<6, 3, 2><<<grid, 128, 2 * STAGE_BYTES>>>(qh, kh, p,
            CDIM, CDIM, CDIM, LDIM, CL, CL, LL, nullptr, attn_scale, nullptr,
            rsum, nullptr, nullptr, nullptr);
    }

    // 3) Final: out[o,l] = sum_j p[l,j]*uT[o,j] / rsum[l] + b2[o] + x[o,l]
    {
        dim3 grid(LDIM / 128, CDIM / 128, BDIM);
        gemm_h<8, 3, 2><<<grid, 128, 2 * STAGE_BYTES>>>(uTh, p, out,
            LDIM, LDIM, LDIM, LDIM, CL, LL, CL, b2, 0.f, x,
            rsum, nullptr, nullptr, nullptr);
    }
}

// round 15
// speedup vs baseline: 1.0312x; 1.0312x over previous
#include <cuda_runtime.h>
#include <cuda_fp16.h>
#include <cstdint>

// Problem: x [B=8, C=512, L=2048], GroupNorm(32) -> QKV -> attention -> O-proj + residual.
// Algebra: out = Pn @ (h @ (Wo·Wv)^T) + (Wo·bv + bo) + x   (softmax rows sum to 1)
#define BDIM 8
#define CDIM 512
#define LDIM 2048
#define NGRP 32
#define CPG  (CDIM / NGRP)   // 16
#define GN_EPS 1e-5f
#define EXP_SHIFT 4.0f

#define CL 1048576LL   // C*L per-batch elems
#define LL 4194304LL   // L*L per-batch elems

// Scratch (bytes):
//  ht   [B,L,C] fp16 @ 0
//  qh   [B,L,C] fp16 @ 16777216
//  kh   [B,L,C] fp16 @ 33554432
//  uTh  [B,C,L] fp16 @ 50331648
//  rsum [B,L]  fp32 @ 67108864
//  b2   [C]    fp32 @ 67174400
//  p    [B,L,L] fp16 @ 83886080
//  wh   [3C,C] fp16 @ 150994944      (wq | wk | W2)
__device__ __align__(256) unsigned char g_scratch[152567808];

// ---------------------------------------------------------------------------
__device__ __forceinline__ float warp_sum(float v) {
#pragma unroll
    for (int o = 16; o > 0; o >>= 1) v += __shfl_xor_sync(0xFFFFFFFFu, v, o);
    return v;
}
__device__ __forceinline__ void mma_f16(float* c, const uint32_t* a, const uint32_t* b) {
    asm volatile(
        "mma.sync.aligned.m16n8k16.row.col.f32.f16.f16.f32 "
        "{%0,%1,%2,%3}, {%4,%5,%6,%7}, {%8,%9}, {%0,%1,%2,%3};"
        : "+f"(c[0]), "+f"(c[1]), "+f"(c[2]), "+f"(c[3])
        : "r"(a[0]), "r"(a[1]), "r"(a[2]), "r"(a[3]), "r"(b[0]), "r"(b[1]));
}
__device__ __forceinline__ void ldsm_x4(uint32_t& r0, uint32_t& r1, uint32_t& r2,
                                        uint32_t& r3, uint32_t addr) {
    asm volatile("ldmatrix.sync.aligned.m8n8.x4.shared.b16 {%0,%1,%2,%3}, [%4];"
                 : "=r"(r0), "=r"(r1), "=r"(r2), "=r"(r3) : "r"(addr));
}
__device__ __forceinline__ void cp_async16(uint32_t dst, const void* src) {
    asm volatile("cp.async.cg.shared.global [%0], [%1], 16;" :: "r"(dst), "l"(src));
}
__device__ __forceinline__ void cp_commit() {
    asm volatile("cp.async.commit_group;" ::: "memory");
}
template<int N>
__device__ __forceinline__ void cp_wait() {
    asm volatile("cp.async.wait_group %0;" :: "n"(N) : "memory");
}

// ============================================================================
// Prologue (one launch, all-independent pieces):
//  blocks [0,256)      : GroupNorm + transpose  x -> ht [B,L,C] fp16
//  blocks [256,2304)   : convert wq -> wh slot0, wk -> wh slot1; zero rsum
//  blocks [2304,2368)  : b2[o] = wo[o,:]·bv + bo[o]
//  blocks [2368,2624)  : W2 = Wo @ Wv in fp32 (32x32 tiles) -> wh slot2 (fp16)
// ============================================================================
__global__ __launch_bounds__(256)
void prep_kernel(const float* __restrict__ x, const float* __restrict__ gamma,
                 const float* __restrict__ beta, __half* __restrict__ ht,
                 const float* __restrict__ wq, const float* __restrict__ wk,
                 const float* __restrict__ wv, const float* __restrict__ wo,
                 const float* __restrict__ bv, const float* __restrict__ bo,
                 __half* __restrict__ wh, float* __restrict__ rsum,
                 float* __restrict__ b2) {
    __shared__ float sh1[8], sh2[8];
    __shared__ float scg[CPG], sbg[CPG];
    __shared__ float tile[CPG][133];
    __shared__ float woS[32][65];
    __shared__ float wvS[64][33];

    const int bid = blockIdx.x;
    const int tid = threadIdx.x;

    if (bid < 256) {
        // ---------------- GroupNorm + transpose ----------------
        const int b = bid / NGRP;
        const int g = bid % NGRP;
        const size_t base = ((size_t)b * CDIM + (size_t)g * CPG) * LDIM;
        const float4* xp = reinterpret_cast<const float4*>(x + base);

        const int n4 = CPG * LDIM / 4;  // 8192
        float s = 0.f, ss = 0.f;
        for (int i = tid; i < n4; i += 256) {
            float4 t = xp[i];
            s  += t.x + t.y + t.z + t.w;
            ss += t.x * t.x + t.y * t.y + t.z * t.z + t.w * t.w;
        }
        int lane = tid & 31, wid = tid >> 5;
        s = warp_sum(s); ss = warp_sum(ss);
        if (lane == 0) { sh1[wid] = s; sh2[wid] = ss; }
        __syncthreads();
        if (wid == 0) {
            s  = (lane < 8) ? sh1[lane] : 0.f;
            ss = (lane < 8) ? sh2[lane] : 0.f;
            s = warp_sum(s); ss = warp_sum(ss);
            if (lane == 0) { sh1[0] = s; sh2[0] = ss; }
        }
        __syncthreads();
        const float inv_n = 1.f / (float)(CPG * LDIM);
        const float mean = sh1[0] * inv_n;
        const float var  = sh2[0] * inv_n - mean * mean;
        const float rstd = rsqrtf(var + GN_EPS);
        if (tid < CPG) {
            float sc = gamma[g * CPG + tid] * rstd;
            scg[tid] = sc;
            sbg[tid] = beta[g * CPG + tid] - mean * sc;
        }
        __syncthreads();

        for (int l0 = 0; l0 < LDIM; l0 += 128) {
            for (int it = tid; it < 512; it += 256) {
                int c  = it >> 5;
                int l4 = (it & 31) * 4;
                float4 t = *reinterpret_cast<const float4*>(
                    &x[base + (size_t)c * LDIM + l0 + l4]);
                float sc = scg[c], sb = sbg[c];
                tile[c][l4 + 0] = t.x * sc + sb;
                tile[c][l4 + 1] = t.y * sc + sb;
                tile[c][l4 + 2] = t.z * sc + sb;
                tile[c][l4 + 3] = t.w * sc + sb;
            }
            __syncthreads();
            for (int it = tid; it < 512; it += 256) {
                int l  = it >> 2;
                int c4 = (it & 3) * 4;
                __half2* dst = reinterpret_cast<__half2*>(
                    ht + ((size_t)b * LDIM + l0 + l) * CDIM + g * CPG + c4);
                dst[0] = __floats2half2_rn(tile[c4 + 0][l], tile[c4 + 1][l]);
                dst[1] = __floats2half2_rn(tile[c4 + 2][l], tile[c4 + 3][l]);
            }
            __syncthreads();
        }
    } else if (bid < 2304) {
        // ---------------- convert wq, wk; zero rsum ----------------
        int i = (bid - 256) * 256 + tid;           // 0 .. 524287
        int which = i >> 18;                       // 0=wq, 1=wk
        int off = i & 0x3FFFF;
        wh[which * 262144 + off] = __float2half(which == 0 ? wq[off] : wk[off]);
        if (i < BDIM * LDIM) rsum[i] = 0.f;
    } else if (bid < 2368) {
        // ---------------- b2 = Wo @ bv + bo ----------------
        const int o = (bid - 2304) * 8 + (tid >> 5);
        const int lane = tid & 31;
        float s = 0.f;
        for (int c = lane; c < CDIM; c += 32) s += wo[o * CDIM + c] * bv[c];
        s = warp_sum(s);
        if (lane == 0) b2[o] = s + bo[o];
    } else {
        // ---------------- W2 = Wo @ Wv (fp32) -> wh slot2 fp16 ----------------
        const int bidx = bid - 2368;               // 0..255
        const int mo = (bidx >> 4) * 32;           // Wo row block
        const int eo = (bidx & 15) * 32;           // Wv col block
        const int tr = (tid >> 4) * 2;
        const int tc = (tid & 15) * 2;
        float a00 = 0.f, a01 = 0.f, a10 = 0.f, a11 = 0.f;

        for (int k0 = 0; k0 < CDIM; k0 += 64) {
#pragma unroll
            for (int t = 0; t < 8; t++) {
                int idx = tid + t * 256;
                int r = idx >> 6, c = idx & 63;
                woS[r][c] = wo[(mo + r) * CDIM + k0 + c];
                int r2 = idx >> 5, c2 = idx & 31;
                wvS[r2][c2] = wv[(k0 + r2) * CDIM + eo + c2];
            }
            __syncthreads();
#pragma unroll 8
            for (int k = 0; k < 64; k++) {
                float w0 = woS[tr][k], w1 = woS[tr + 1][k];
                float v0 = wvS[k][tc], v1 = wvS[k][tc + 1];
                a00 += w0 * v0; a01 += w0 * v1;
                a10 += w1 * v0; a11 += w1 * v1;
            }
            __syncthreads();
        }
        __half* w2 = wh + 524288;
        *reinterpret_cast<__half2*>(&w2[(mo + tr) * CDIM + eo + tc]) =
            __floats2half2_rn(a00, a01);
        *reinterpret_cast<__half2*>(&w2[(mo + tr + 1) * CDIM + eo + tc]) =
            __floats2half2_rn(a10, a11);
    }
}

// ============================================================================
// fp16 tensor-core GEMM: D[m,n] = sum_k A[m,k]*B[n,k]  (A:[M,K], B:[N,K] fp16)
// CTA: 128 thr (4 warps), 128x128 tile, warp tile 64x64 (2x2 warp grid).
// K-chunk 64 halves, 3-stage cp.async, XOR swizzle, ldmatrix fragment loads.
// (R11 proven config: __launch_bounds__(128,2), 2 CTAs/SM.)
// EPI: 5 = merged QKU routing (q/k row-major + bias, u transposed no bias)
//      6 = scores: P = fp16(exp(c*alpha - EXP_SHIFT)), atomic row sums -> rsum
//      8 = final: fp32 out = c/rsum[n] + bias[m] + resid[m*ldc+n]
// ============================================================================
#define STAGE_BYTES 32768
#define GEMM_SMEM   (3 * STAGE_BYTES)

template<int EPI>
__global__ __launch_bounds__(128, 2)
void gemm_h(const __half* __restrict__ A, const __half* __restrict__ B,
            void* __restrict__ Dv, int K, int lda, int ldb, int ldc,
            long long sA, long long sB, long long sD,
            const float* __restrict__ bias, float alpha,
            const float* __restrict__ resid, float* __restrict__ rsum,
            void* __restrict__ Dv2, void* __restrict__ Dv3,
            const float* __restrict__ bias2) {
    extern __shared__ char smem[];
    const uint32_t sb = (uint32_t)__cvta_generic_to_shared(smem);
    const int tid = threadIdx.x;
    const int lane = tid & 31;
    const int warp = tid >> 5;
    const int gid = lane >> 2;
    const int tig = lane & 3;
    const int wm = warp & 1;
    const int wn = warp >> 1;
    const int m0 = blockIdx.y * 128;
    const int n0 = blockIdx.x * 128;
    const int bz = blockIdx.z;

    A += (long long)bz * sA;
    B += (long long)bz * sB;

    const int lm = tid >> 3;
    const int lg = tid & 7;
    const __half* Ap = A + (long long)(m0 + lm) * lda + lg * 8;
    const __half* Bp = B + (long long)(n0 + lm) * ldb + lg * 8;
    const uint32_t sts_off = (uint32_t)(lm * 128 + (((lg ^ lm) & 7) << 4));

    const int r7 = lane & 7;
    const int lhi = lane >> 4;
    const int arow = ((lane >> 3) & 1) * 8 + r7;
    const int bhi = (lane >> 3) & 1;
    const int brow = ((lane >> 4) & 1) * 8 + r7;
    uint32_t aRowOff[4], bRowOff[4];
#pragma unroll
    for (int mt = 0; mt < 4; mt++)
        aRowOff[mt] = (uint32_t)((wm * 64 + mt * 16 + arow) * 128);
#pragma unroll
    for (int j = 0; j < 4; j++)
        bRowOff[j] = (uint32_t)((wn * 64 + j * 16 + brow) * 128) + 16384u;

    const int nch = K / 64;

#define ISSUE_STAGE(st, buf) do {                                             \
        const uint32_t d0 = sb + (uint32_t)(buf) * STAGE_BYTES + sts_off;     \
        const __half* ap = Ap + (st) * 64;                                    \
        const __half* bp = Bp + (st) * 64;                                    \
        _Pragma("unroll")                                                     \
        for (int u = 0; u < 8; u++)                                           \
            cp_async16(d0 + u * 2048, ap + (long long)u * 16 * lda);          \
        _Pragma("unroll")                                                     \
        for (int u = 0; u < 8; u++)                                           \
            cp_async16(d0 + 16384 + u * 2048, bp + (long long)u * 16 * ldb);  \
    } while (0)

    ISSUE_STAGE(0, 0); cp_commit();
    ISSUE_STAGE(1, 1); cp_commit();

    float acc[4][8][4];
#pragma unroll
    for (int i = 0; i < 4; i++)
#pragma unroll
        for (int j = 0; j < 8; j++)
#pragma unroll
            for (int r = 0; r < 4; r++) acc[i][j][r] = 0.f;

    for (int i = 0; i < nch; i++) {
        cp_wait<1>();
        __syncthreads();
        if (i + 2 < nch) ISSUE_STAGE(i + 2, (i + 2) % 3);
        cp_commit();

        const uint32_t stage = sb + (uint32_t)(i % 3) * STAGE_BYTES;
#pragma unroll
        for (int ks = 0; ks < 4; ks++) {
            const uint32_t swa = (uint32_t)((((2 * ks + lhi) ^ r7) & 7) << 4);
            const uint32_t swb = (uint32_t)((((2 * ks + bhi) ^ r7) & 7) << 4);
            uint32_t afr[4][4], bfr[8][2];
#pragma unroll
            for (int mt = 0; mt < 4; mt++)
                ldsm_x4(afr[mt][0], afr[mt][1], afr[mt][2], afr[mt][3],
                        stage + aRowOff[mt] + swa);
#pragma unroll
            for (int j = 0; j < 4; j++)
                ldsm_x4(bfr[2 * j][0], bfr[2 * j][1], bfr[2 * j + 1][0],
                        bfr[2 * j + 1][1], stage + bRowOff[j] + swb);
#pragma unroll
            for (int mt = 0; mt < 4; mt++)
#pragma unroll
                for (int nt = 0; nt < 8; nt++)
                    mma_f16(acc[mt][nt], afr[mt], bfr[nt]);
        }
    }
#undef ISSUE_STAGE

    // EPI 8: per-column inverse attention row-sums (n indexes the L axis)
    float invn[8][2];
    if (EPI == 8) {
#pragma unroll
        for (int nt = 0; nt < 8; nt++) {
            const int n = n0 + wn * 64 + nt * 8 + tig * 2;
            invn[nt][0] = 1.f / rsum[(long long)bz * LDIM + n];
            invn[nt][1] = 1.f / rsum[(long long)bz * LDIM + n + 1];
        }
    }

#pragma unroll
    for (int mt = 0; mt < 4; mt++) {
        const int m = m0 + wm * 64 + mt * 16 + gid;
        float rs0 = 0.f, rs1 = 0.f;
#pragma unroll
        for (int nt = 0; nt < 8; nt++) {
            const int n = n0 + wn * 64 + nt * 8 + tig * 2;
            float* c = acc[mt][nt];
            if (EPI == 5) {
                const int which = n >> 9;          // 0=q, 1=k, 2=u
                const int nl = n & 511;
                if (which < 2) {
                    __half* Dh = ((which == 0) ? (__half*)Dv : (__half*)Dv2)
                                 + (long long)bz * CL;
                    const float* bb = (which == 0) ? bias : bias2;
                    const float b0v = bb[nl], b1v = bb[nl + 1];
                    *reinterpret_cast<__half2*>(Dh + (long long)m * CDIM + nl) =
                        __floats2half2_rn(c[0] + b0v, c[1] + b1v);
                    *reinterpret_cast<__half2*>(Dh + (long long)(m + 8) * CDIM + nl) =
                        __floats2half2_rn(c[2] + b0v, c[3] + b1v);
                } else {
                    __half* Dh = (__half*)Dv3 + (long long)bz * CL;
                    Dh[(long long)nl * LDIM + m]           = __float2half(c[0]);
                    Dh[(long long)(nl + 1) * LDIM + m]     = __float2half(c[1]);
                    Dh[(long long)nl * LDIM + m + 8]       = __float2half(c[2]);
                    Dh[(long long)(nl + 1) * LDIM + m + 8] = __float2half(c[3]);
                }
            } else if (EPI == 6) {
                __half* Dh = (__half*)Dv + (long long)bz * sD;
                const float e0 = __expf(c[0] * alpha - EXP_SHIFT);
                const float e1 = __expf(c[1] * alpha - EXP_SHIFT);
                const float e2 = __expf(c[2] * alpha - EXP_SHIFT);
                const float e3 = __expf(c[3] * alpha - EXP_SHIFT);
                *reinterpret_cast<__half2*>(Dh + (long long)m * ldc + n) =
                    __floats2half2_rn(e0, e1);
                *reinterpret_cast<__half2*>(Dh + (long long)(m + 8) * ldc + n) =
                    __floats2half2_rn(e2, e3);
                rs0 += e0 + e1;
                rs1 += e2 + e3;
            } else {  // EPI == 8
                float* Df = (float*)Dv + (long long)bz * sD;
                const float* rs = resid + (long long)bz * sD;
                const float bm0 = bias[m], bm1 = bias[m + 8];
                const float2 r0 = *reinterpret_cast<const float2*>(
                    &rs[(long long)m * ldc + n]);
                const float2 r1 = *reinterpret_cast<const float2*>(
                    &rs[(long long)(m + 8) * ldc + n]);
                *reinterpret_cast<float2*>(&Df[(long long)m * ldc + n]) =
                    make_float2(c[0] * invn[nt][0] + bm0 + r0.x,
                                c[1] * invn[nt][1] + bm0 + r0.y);
                *reinterpret_cast<float2*>(&Df[(long long)(m + 8) * ldc + n]) =
                    make_float2(c[2] * invn[nt][0] + bm1 + r1.x,
                                c[3] * invn[nt][1] + bm1 + r1.y);
            }
        }
        if (EPI == 6) {
            rs0 += __shfl_xor_sync(0xFFFFFFFFu, rs0, 1);
            rs0 += __shfl_xor_sync(0xFFFFFFFFu, rs0, 2);
            rs1 += __shfl_xor_sync(0xFFFFFFFFu, rs1, 1);
            rs1 += __shfl_xor_sync(0xFFFFFFFFu, rs1, 2);
            if (tig == 0) {
                atomicAdd(&rsum[(long long)bz * LDIM + m], rs0);
                atomicAdd(&rsum[(long long)bz * LDIM + m + 8], rs1);
            }
        }
    }
}

// ============================================================================
// Launch
// ============================================================================
extern "C" void kernel_launch(void* const* d_in, const int* in_sizes, int n_in,
                              void* d_out, int out_size) {
    (void)in_sizes; (void)n_in; (void)out_size;
    const float* x   = (const float*)d_in[0];
    const float* gns = (const float*)d_in[1];
    const float* gnb = (const float*)d_in[2];
    const float* wq  = (const float*)d_in[3];
    const float* bq  = (const float*)d_in[4];
    const float* wk  = (const float*)d_in[5];
    const float* bk  = (const float*)d_in[6];
    const float* wv  = (const float*)d_in[7];
    const float* bv  = (const float*)d_in[8];
    const float* wo  = (const float*)d_in[9];
    const float* bo  = (const float*)d_in[10];
    float* out = (float*)d_out;

    unsigned char* base = nullptr;
    cudaGetSymbolAddress((void**)&base, g_scratch);
    __half* ht   = (__half*)(base);
    __half* qh   = (__half*)(base + 16777216);
    __half* kh   = (__half*)(base + 33554432);
    __half* uTh  = (__half*)(base + 50331648);
    float*  rsum = (float*)(base + 67108864);
    float*  b2   = (float*)(base + 67174400);
    __half* p    = (__half*)(base + 83886080);
    __half* wh   = (__half*)(base + 150994944);   // [wq | wk | W2]

    const float attn_scale = 0.044194173824159216f;  // 512^-0.5

    static bool attr_done = false;
    if (!attr_done) {
        cudaFuncSetAttribute(gemm_h<5>, cudaFuncAttributeMaxDynamicSharedMemorySize, GEMM_SMEM);
        cudaFuncSetAttribute(gemm_h<6>, cudaFuncAttributeMaxDynamicSharedMemorySize, GEMM_SMEM);
        cudaFuncSetAttribute(gemm_h<8>, cudaFuncAttributeMaxDynamicSharedMemorySize, GEMM_SMEM);
        attr_done = true;
    }

    // 0) Prologue: gn+transpose | wq/wk convert + rsum | b2 | W2 (fp32) — one launch
    prep_kernel<<<2624, 256>>>(x, gns, gnb, ht, wq, wk, wv, wo, bv, bo,
                               wh, rsum, b2);

    // 1) Merged QKU projection: M=L, N=3C=1536, K=C
    {
        dim3 grid(1536 / 128, LDIM / 128, BDIM);
        gemm_h<5><<<grid, 128, GEMM_SMEM>>>(ht, wh, qh, CDIM, CDIM, CDIM, CDIM,
            CL, 0, CL, bq, 0.f, nullptr, nullptr, kh, uTh, bk);
    }

    // 2) Scores fused with exp: p[i,j] = fp16(exp(scale*q.k - 4)), rsum[i] += ...
    {
        dim3 grid(LDIM / 128, LDIM / 128, BDIM);
        gemm_h<6><<<grid, 128, GEMM_SMEM>>>(qh, kh, p, CDIM, CDIM, CDIM, LDIM,
            CL, CL, LL, nullptr, attn_scale, nullptr, rsum, nullptr, nullptr,
            nullptr);
    }

    // 3) Final: out[o,l] = sum_j p[l,j]*uT[o,j] / rsum[l] + b2[o] + x[o,l]
    {
        dim3 grid(LDIM / 128, CDIM / 128, BDIM);
        gemm_h<8><<<grid, 128, GEMM_SMEM>>>(uTh, p, out, LDIM, LDIM, LDIM, LDIM,
            CL, LL, CL, b2, 0.f, x, rsum, nullptr, nullptr, nullptr);
    }
}

// round 16
// speedup vs baseline: 1.0327x; 1.0015x over previous
#include <cuda_runtime.h>
#include <cuda_fp16.h>
#include <cstdint>

// Problem: x [B=8, C=512, L=2048], GroupNorm(32) -> QKV -> attention -> O-proj + residual.
// Algebra: out = Pn @ (h @ (Wo·Wv)^T) + (Wo·bv + bo) + x   (softmax rows sum to 1)
#define BDIM 8
#define CDIM 512
#define LDIM 2048
#define NGRP 32
#define CPG  (CDIM / NGRP)   // 16
#define GN_EPS 1e-5f
#define EXP_SHIFT 4.0f

#define CL 1048576LL   // C*L per-batch elems
#define LL 4194304LL   // L*L per-batch elems

// Scratch (bytes):
//  ht   [B,L,C] fp16 @ 0
//  qh   [B,L,C] fp16 @ 16777216
//  kh   [B,L,C] fp16 @ 33554432
//  uTh  [B,C,L] fp16 @ 50331648
//  rsum [B,L]  fp32 @ 67108864
//  b2   [C]    fp32 @ 67174400
//  p    [B,L,L] fp16 @ 83886080
//  wh   [3C,C] fp16 @ 150994944      (wq | wk | W2)
__device__ __align__(256) unsigned char g_scratch[152567808];

// ---------------------------------------------------------------------------
__device__ __forceinline__ float warp_sum(float v) {
#pragma unroll
    for (int o = 16; o > 0; o >>= 1) v += __shfl_xor_sync(0xFFFFFFFFu, v, o);
    return v;
}
__device__ __forceinline__ void mma_f16(float* c, const uint32_t* a, const uint32_t* b) {
    asm volatile(
        "mma.sync.aligned.m16n8k16.row.col.f32.f16.f16.f32 "
        "{%0,%1,%2,%3}, {%4,%5,%6,%7}, {%8,%9}, {%0,%1,%2,%3};"
        : "+f"(c[0]), "+f"(c[1]), "+f"(c[2]), "+f"(c[3])
        : "r"(a[0]), "r"(a[1]), "r"(a[2]), "r"(a[3]), "r"(b[0]), "r"(b[1]));
}
__device__ __forceinline__ void ldsm_x4(uint32_t& r0, uint32_t& r1, uint32_t& r2,
                                        uint32_t& r3, uint32_t addr) {
    asm volatile("ldmatrix.sync.aligned.m8n8.x4.shared.b16 {%0,%1,%2,%3}, [%4];"
                 : "=r"(r0), "=r"(r1), "=r"(r2), "=r"(r3) : "r"(addr));
}
__device__ __forceinline__ void cp_async16(uint32_t dst, const void* src) {
    asm volatile("cp.async.cg.shared.global [%0], [%1], 16;" :: "r"(dst), "l"(src));
}
__device__ __forceinline__ void cp_commit() {
    asm volatile("cp.async.commit_group;" ::: "memory");
}
template<int N>
__device__ __forceinline__ void cp_wait() {
    asm volatile("cp.async.wait_group %0;" :: "n"(N) : "memory");
}

// ============================================================================
// Prologue (one launch, all-independent pieces):
//  blocks [0,256)      : GroupNorm + transpose  x -> ht [B,L,C] fp16
//  blocks [256,2304)   : convert wq -> wh slot0, wk -> wh slot1; zero rsum
//  blocks [2304,2368)  : b2[o] = wo[o,:]·bv + bo[o]
//  blocks [2368,2624)  : W2 = Wo @ Wv in fp32 (32x32 tiles) -> wh slot2 (fp16)
// ============================================================================
__global__ __launch_bounds__(256)
void prep_kernel(const float* __restrict__ x, const float* __restrict__ gamma,
                 const float* __restrict__ beta, __half* __restrict__ ht,
                 const float* __restrict__ wq, const float* __restrict__ wk,
                 const float* __restrict__ wv, const float* __restrict__ wo,
                 const float* __restrict__ bv, const float* __restrict__ bo,
                 __half* __restrict__ wh, float* __restrict__ rsum,
                 float* __restrict__ b2) {
    __shared__ float sh1[8], sh2[8];
    __shared__ float scg[CPG], sbg[CPG];
    __shared__ float tile[CPG][133];
    __shared__ float woS[32][65];
    __shared__ float wvS[64][33];

    const int bid = blockIdx.x;
    const int tid = threadIdx.x;

    if (bid < 256) {
        // ---------------- GroupNorm + transpose ----------------
        const int b = bid / NGRP;
        const int g = bid % NGRP;
        const size_t base = ((size_t)b * CDIM + (size_t)g * CPG) * LDIM;
        const float4* xp = reinterpret_cast<const float4*>(x + base);

        const int n4 = CPG * LDIM / 4;  // 8192
        float s = 0.f, ss = 0.f;
        for (int i = tid; i < n4; i += 256) {
            float4 t = xp[i];
            s  += t.x + t.y + t.z + t.w;
            ss += t.x * t.x + t.y * t.y + t.z * t.z + t.w * t.w;
        }
        int lane = tid & 31, wid = tid >> 5;
        s = warp_sum(s); ss = warp_sum(ss);
        if (lane == 0) { sh1[wid] = s; sh2[wid] = ss; }
        __syncthreads();
        if (wid == 0) {
            s  = (lane < 8) ? sh1[lane] : 0.f;
            ss = (lane < 8) ? sh2[lane] : 0.f;
            s = warp_sum(s); ss = warp_sum(ss);
            if (lane == 0) { sh1[0] = s; sh2[0] = ss; }
        }
        __syncthreads();
        const float inv_n = 1.f / (float)(CPG * LDIM);
        const float mean = sh1[0] * inv_n;
        const float var  = sh2[0] * inv_n - mean * mean;
        const float rstd = rsqrtf(var + GN_EPS);
        if (tid < CPG) {
            float sc = gamma[g * CPG + tid] * rstd;
            scg[tid] = sc;
            sbg[tid] = beta[g * CPG + tid] - mean * sc;
        }
        __syncthreads();

        for (int l0 = 0; l0 < LDIM; l0 += 128) {
            for (int it = tid; it < 512; it += 256) {
                int c  = it >> 5;
                int l4 = (it & 31) * 4;
                float4 t = *reinterpret_cast<const float4*>(
                    &x[base + (size_t)c * LDIM + l0 + l4]);
                float sc = scg[c], sb = sbg[c];
                tile[c][l4 + 0] = t.x * sc + sb;
                tile[c][l4 + 1] = t.y * sc + sb;
                tile[c][l4 + 2] = t.z * sc + sb;
                tile[c][l4 + 3] = t.w * sc + sb;
            }
            __syncthreads();
            for (int it = tid; it < 512; it += 256) {
                int l  = it >> 2;
                int c4 = (it & 3) * 4;
                __half2* dst = reinterpret_cast<__half2*>(
                    ht + ((size_t)b * LDIM + l0 + l) * CDIM + g * CPG + c4);
                dst[0] = __floats2half2_rn(tile[c4 + 0][l], tile[c4 + 1][l]);
                dst[1] = __floats2half2_rn(tile[c4 + 2][l], tile[c4 + 3][l]);
            }
            __syncthreads();
        }
    } else if (bid < 2304) {
        // ---------------- convert wq, wk; zero rsum ----------------
        int i = (bid - 256) * 256 + tid;           // 0 .. 524287
        int which = i >> 18;                       // 0=wq, 1=wk
        int off = i & 0x3FFFF;
        wh[which * 262144 + off] = __float2half(which == 0 ? wq[off] : wk[off]);
        if (i < BDIM * LDIM) rsum[i] = 0.f;
    } else if (bid < 2368) {
        // ---------------- b2 = Wo @ bv + bo ----------------
        const int o = (bid - 2304) * 8 + (tid >> 5);
        const int lane = tid & 31;
        float s = 0.f;
        for (int c = lane; c < CDIM; c += 32) s += wo[o * CDIM + c] * bv[c];
        s = warp_sum(s);
        if (lane == 0) b2[o] = s + bo[o];
    } else {
        // ---------------- W2 = Wo @ Wv (fp32) -> wh slot2 fp16 ----------------
        const int bidx = bid - 2368;               // 0..255
        const int mo = (bidx >> 4) * 32;           // Wo row block
        const int eo = (bidx & 15) * 32;           // Wv col block
        const int tr = (tid >> 4) * 2;
        const int tc = (tid & 15) * 2;
        float a00 = 0.f, a01 = 0.f, a10 = 0.f, a11 = 0.f;

        for (int k0 = 0; k0 < CDIM; k0 += 64) {
#pragma unroll
            for (int t = 0; t < 8; t++) {
                int idx = tid + t * 256;
                int r = idx >> 6, c = idx & 63;
                woS[r][c] = wo[(mo + r) * CDIM + k0 + c];
                int r2 = idx >> 5, c2 = idx & 31;
                wvS[r2][c2] = wv[(k0 + r2) * CDIM + eo + c2];
            }
            __syncthreads();
#pragma unroll 8
            for (int k = 0; k < 64; k++) {
                float w0 = woS[tr][k], w1 = woS[tr + 1][k];
                float v0 = wvS[k][tc], v1 = wvS[k][tc + 1];
                a00 += w0 * v0; a01 += w0 * v1;
                a10 += w1 * v0; a11 += w1 * v1;
            }
            __syncthreads();
        }
        __half* w2 = wh + 524288;
        *reinterpret_cast<__half2*>(&w2[(mo + tr) * CDIM + eo + tc]) =
            __floats2half2_rn(a00, a01);
        *reinterpret_cast<__half2*>(&w2[(mo + tr + 1) * CDIM + eo + tc]) =
            __floats2half2_rn(a10, a11);
    }
}

// ============================================================================
// fp16 tensor-core GEMM: D[m,n] = sum_k A[m,k]*B[n,k]  (A:[M,K], B:[N,K] fp16)
// CTA: 128 thr (4 warps), 128x128 tile, warp tile 64x64 (2x2 warp grid).
// K-chunk 64 halves, 3-stage cp.async, XOR swizzle, ldmatrix fragment loads.
// cp.async prefetch interleaved: 4 issues per k-step (avoids MIO burst that
// head-of-line-blocks ldmatrix); one commit per chunk.
// Register double-buffered fragments (R11 proven config, launch_bounds(128,2)).
// EPI: 5 = merged QKU routing (q/k row-major + bias, u transposed no bias)
//      6 = scores: P = fp16(exp(c*alpha - EXP_SHIFT)), atomic row sums -> rsum
//      8 = final: fp32 out = c/rsum[n] + bias[m] + resid[m*ldc+n]
// ============================================================================
#define STAGE_BYTES 32768
#define GEMM_SMEM   (3 * STAGE_BYTES)

template<int EPI>
__global__ __launch_bounds__(128, 2)
void gemm_h(const __half* __restrict__ A, const __half* __restrict__ B,
            void* __restrict__ Dv, int K, int lda, int ldb, int ldc,
            long long sA, long long sB, long long sD,
            const float* __restrict__ bias, float alpha,
            const float* __restrict__ resid, float* __restrict__ rsum,
            void* __restrict__ Dv2, void* __restrict__ Dv3,
            const float* __restrict__ bias2) {
    extern __shared__ char smem[];
    const uint32_t sb = (uint32_t)__cvta_generic_to_shared(smem);
    const int tid = threadIdx.x;
    const int lane = tid & 31;
    const int warp = tid >> 5;
    const int gid = lane >> 2;
    const int tig = lane & 3;
    const int wm = warp & 1;
    const int wn = warp >> 1;
    const int m0 = blockIdx.y * 128;
    const int n0 = blockIdx.x * 128;
    const int bz = blockIdx.z;

    A += (long long)bz * sA;
    B += (long long)bz * sB;

    const int lm = tid >> 3;
    const int lg = tid & 7;
    const __half* Ap = A + (long long)(m0 + lm) * lda + lg * 8;
    const __half* Bp = B + (long long)(n0 + lm) * ldb + lg * 8;
    const uint32_t sts_off = (uint32_t)(lm * 128 + (((lg ^ lm) & 7) << 4));

    const int r7 = lane & 7;
    const int lhi = lane >> 4;
    const int arow = ((lane >> 3) & 1) * 8 + r7;
    const int bhi = (lane >> 3) & 1;
    const int brow = ((lane >> 4) & 1) * 8 + r7;
    uint32_t aRowOff[4], bRowOff[4];
#pragma unroll
    for (int mt = 0; mt < 4; mt++)
        aRowOff[mt] = (uint32_t)((wm * 64 + mt * 16 + arow) * 128);
#pragma unroll
    for (int j = 0; j < 4; j++)
        bRowOff[j] = (uint32_t)((wn * 64 + j * 16 + brow) * 128) + 16384u;

    const int nch = K / 64;

// full-chunk issue (prologue only)
#define ISSUE_STAGE(st, buf) do {                                             \
        const uint32_t d0 = sb + (uint32_t)(buf) * STAGE_BYTES + sts_off;     \
        const __half* ap = Ap + (st) * 64;                                    \
        const __half* bp = Bp + (st) * 64;                                    \
        _Pragma("unroll")                                                     \
        for (int u = 0; u < 8; u++)                                           \
            cp_async16(d0 + u * 2048, ap + (long long)u * 16 * lda);          \
        _Pragma("unroll")                                                     \
        for (int u = 0; u < 8; u++)                                           \
            cp_async16(d0 + 16384 + u * 2048, bp + (long long)u * 16 * ldb);  \
    } while (0)

// quarter-chunk issue: 2 A rows + 2 B rows (u = 2q, 2q+1)
#define ISSUE_Q(st, buf, q) do {                                              \
        const uint32_t d0 = sb + (uint32_t)(buf) * STAGE_BYTES + sts_off;     \
        const __half* ap = Ap + (st) * 64;                                    \
        const __half* bp = Bp + (st) * 64;                                    \
        cp_async16(d0 + (2 * (q)) * 2048,                                     \
                   ap + (long long)(2 * (q)) * 16 * lda);                     \
        cp_async16(d0 + (2 * (q) + 1) * 2048,                                 \
                   ap + (long long)(2 * (q) + 1) * 16 * lda);                 \
        cp_async16(d0 + 16384 + (2 * (q)) * 2048,                             \
                   bp + (long long)(2 * (q)) * 16 * ldb);                     \
        cp_async16(d0 + 16384 + (2 * (q) + 1) * 2048,                         \
                   bp + (long long)(2 * (q) + 1) * 16 * ldb);                 \
    } while (0)

// load one k-step's fragments into register buffer slot `sl`
#define LOAD_FRAGS(sl, ks_) do {                                              \
        const uint32_t swa = (uint32_t)((((2 * (ks_) + lhi) ^ r7) & 7) << 4); \
        const uint32_t swb = (uint32_t)((((2 * (ks_) + bhi) ^ r7) & 7) << 4); \
        _Pragma("unroll")                                                     \
        for (int mt = 0; mt < 4; mt++)                                        \
            ldsm_x4(afr[sl][mt][0], afr[sl][mt][1], afr[sl][mt][2],           \
                    afr[sl][mt][3], stage + aRowOff[mt] + swa);               \
        _Pragma("unroll")                                                     \
        for (int j = 0; j < 4; j++)                                           \
            ldsm_x4(bfr[sl][2 * j][0], bfr[sl][2 * j][1],                     \
                    bfr[sl][2 * j + 1][0], bfr[sl][2 * j + 1][1],             \
                    stage + bRowOff[j] + swb);                                \
    } while (0)

    ISSUE_STAGE(0, 0); cp_commit();
    ISSUE_STAGE(1, 1); cp_commit();

    float acc[4][8][4];
#pragma unroll
    for (int i = 0; i < 4; i++)
#pragma unroll
        for (int j = 0; j < 8; j++)
#pragma unroll
            for (int r = 0; r < 4; r++) acc[i][j][r] = 0.f;

    uint32_t afr[2][4][4], bfr[2][8][2];

    for (int i = 0; i < nch; i++) {
        cp_wait<1>();
        __syncthreads();

        const uint32_t stage = sb + (uint32_t)(i % 3) * STAGE_BYTES;
        const int pf = i + 2;
        const int pbuf = pf % 3;
        const bool do_pf = (pf < nch);

        LOAD_FRAGS(0, 0);
#pragma unroll
        for (int ks = 0; ks < 4; ks++) {
            if (do_pf) ISSUE_Q(pf, pbuf, ks);
            if (ks < 3) LOAD_FRAGS((ks + 1) & 1, ks + 1);
            const int cur = ks & 1;
#pragma unroll
            for (int mt = 0; mt < 4; mt++)
#pragma unroll
                for (int nt = 0; nt < 8; nt++)
                    mma_f16(acc[mt][nt], afr[cur][mt], bfr[cur][nt]);
        }
        cp_commit();
    }
#undef ISSUE_STAGE
#undef ISSUE_Q
#undef LOAD_FRAGS

    // EPI 8: per-column inverse attention row-sums (n indexes the L axis)
    float invn[8][2];
    if (EPI == 8) {
#pragma unroll
        for (int nt = 0; nt < 8; nt++) {
            const int n = n0 + wn * 64 + nt * 8 + tig * 2;
            invn[nt][0] = 1.f / rsum[(long long)bz * LDIM + n];
            invn[nt][1] = 1.f / rsum[(long long)bz * LDIM + n + 1];
        }
    }

#pragma unroll
    for (int mt = 0; mt < 4; mt++) {
        const int m = m0 + wm * 64 + mt * 16 + gid;
        float rs0 = 0.f, rs1 = 0.f;
#pragma unroll
        for (int nt = 0; nt < 8; nt++) {
            const int n = n0 + wn * 64 + nt * 8 + tig * 2;
            float* c = acc[mt][nt];
            if (EPI == 5) {
                const int which = n >> 9;          // 0=q, 1=k, 2=u
                const int nl = n & 511;
                if (which < 2) {
                    __half* Dh = ((which == 0) ? (__half*)Dv : (__half*)Dv2)
                                 + (long long)bz * CL;
                    const float* bb = (which == 0) ? bias : bias2;
                    const float b0v = bb[nl], b1v = bb[nl + 1];
                    *reinterpret_cast<__half2*>(Dh + (long long)m * CDIM + nl) =
                        __floats2half2_rn(c[0] + b0v, c[1] + b1v);
                    *reinterpret_cast<__half2*>(Dh + (long long)(m + 8) * CDIM + nl) =
                        __floats2half2_rn(c[2] + b0v, c[3] + b1v);
                } else {
                    __half* Dh = (__half*)Dv3 + (long long)bz * CL;
                    Dh[(long long)nl * LDIM + m]           = __float2half(c[0]);
                    Dh[(long long)(nl + 1) * LDIM + m]     = __float2half(c[1]);
                    Dh[(long long)nl * LDIM + m + 8]       = __float2half(c[2]);
                    Dh[(long long)(nl + 1) * LDIM + m + 8] = __float2half(c[3]);
                }
            } else if (EPI == 6) {
                __half* Dh = (__half*)Dv + (long long)bz * sD;
                const float e0 = __expf(c[0] * alpha - EXP_SHIFT);
                const float e1 = __expf(c[1] * alpha - EXP_SHIFT);
                const float e2 = __expf(c[2] * alpha - EXP_SHIFT);
                const float e3 = __expf(c[3] * alpha - EXP_SHIFT);
                *reinterpret_cast<__half2*>(Dh + (long long)m * ldc + n) =
                    __floats2half2_rn(e0, e1);
                *reinterpret_cast<__half2*>(Dh + (long long)(m + 8) * ldc + n) =
                    __floats2half2_rn(e2, e3);
                rs0 += e0 + e1;
                rs1 += e2 + e3;
            } else {  // EPI == 8
                float* Df = (float*)Dv + (long long)bz * sD;
                const float* rs = resid + (long long)bz * sD;
                const float bm0 = bias[m], bm1 = bias[m + 8];
                const float2 r0 = *reinterpret_cast<const float2*>(
                    &rs[(long long)m * ldc + n]);
                const float2 r1 = *reinterpret_cast<const float2*>(
                    &rs[(long long)(m + 8) * ldc + n]);
                *reinterpret_cast<float2*>(&Df[(long long)m * ldc + n]) =
                    make_float2(c[0] * invn[nt][0] + bm0 + r0.x,
                                c[1] * invn[nt][1] + bm0 + r0.y);
                *reinterpret_cast<float2*>(&Df[(long long)(m + 8) * ldc + n]) =
                    make_float2(c[2] * invn[nt][0] + bm1 + r1.x,
                                c[3] * invn[nt][1] + bm1 + r1.y);
            }
        }
        if (EPI == 6) {
            rs0 += __shfl_xor_sync(0xFFFFFFFFu, rs0, 1);
            rs0 += __shfl_xor_sync(0xFFFFFFFFu, rs0, 2);
            rs1 += __shfl_xor_sync(0xFFFFFFFFu, rs1, 1);
            rs1 += __shfl_xor_sync(0xFFFFFFFFu, rs1, 2);
            if (tig == 0) {
                atomicAdd(&rsum[(long long)bz * LDIM + m], rs0);
                atomicAdd(&rsum[(long long)bz * LDIM + m + 8], rs1);
            }
        }
    }
}

// ============================================================================
// Launch
// ============================================================================
extern "C" void kernel_launch(void* const* d_in, const int* in_sizes, int n_in,
                              void* d_out, int out_size) {
    (void)in_sizes; (void)n_in; (void)out_size;
    const float* x   = (const float*)d_in[0];
    const float* gns = (const float*)d_in[1];
    const float* gnb = (const float*)d_in[2];
    const float* wq  = (const float*)d_in[3];
    const float* bq  = (const float*)d_in[4];
    const float* wk  = (const float*)d_in[5];
    const float* bk  = (const float*)d_in[6];
    const float* wv  = (const float*)d_in[7];
    const float* bv  = (const float*)d_in[8];
    const float* wo  = (const float*)d_in[9];
    const float* bo  = (const float*)d_in[10];
    float* out = (float*)d_out;

    unsigned char* base = nullptr;
    cudaGetSymbolAddress((void**)&base, g_scratch);
    __half* ht   = (__half*)(base);
    __half* qh   = (__half*)(base + 16777216);
    __half* kh   = (__half*)(base + 33554432);
    __half* uTh  = (__half*)(base + 50331648);
    float*  rsum = (float*)(base + 67108864);
    float*  b2   = (float*)(base + 67174400);
    __half* p    = (__half*)(base + 83886080);
    __half* wh   = (__half*)(base + 150994944);   // [wq | wk | W2]

    const float attn_scale = 0.044194173824159216f;  // 512^-0.5

    static bool attr_done = false;
    if (!attr_done) {
        cudaFuncSetAttribute(gemm_h<5>, cudaFuncAttributeMaxDynamicSharedMemorySize, GEMM_SMEM);
        cudaFuncSetAttribute(gemm_h<6>, cudaFuncAttributeMaxDynamicSharedMemorySize, GEMM_SMEM);
        cudaFuncSetAttribute(gemm_h<8>, cudaFuncAttributeMaxDynamicSharedMemorySize, GEMM_SMEM);
        attr_done = true;
    }

    // 0) Prologue: gn+transpose | wq/wk convert + rsum | b2 | W2 (fp32) — one launch
    prep_kernel<<<2624, 256>>>(x, gns, gnb, ht, wq, wk, wv, wo, bv, bo,
                               wh, rsum, b2);

    // 1) Merged QKU projection: M=L, N=3C=1536, K=C
    {
        dim3 grid(1536 / 128, LDIM / 128, BDIM);
        gemm_h<5><<<grid, 128, GEMM_SMEM>>>(ht, wh, qh, CDIM, CDIM, CDIM, CDIM,
            CL, 0, CL, bq, 0.f, nullptr, nullptr, kh, uTh, bk);
    }

    // 2) Scores fused with exp: p[i,j] = fp16(exp(scale*q.k - 4)), rsum[i] += ...
    {
        dim3 grid(LDIM / 128, LDIM / 128, BDIM);
        gemm_h<6><<<grid, 128, GEMM_SMEM>>>(qh, kh, p, CDIM, CDIM, CDIM, LDIM,
            CL, CL, LL, nullptr, attn_scale, nullptr, rsum, nullptr, nullptr,
            nullptr);
    }

    // 3) Final: out[o,l] = sum_j p[l,j]*uT[o,j] / rsum[l] + b2[o] + x[o,l]
    {
        dim3 grid(LDIM / 128, CDIM / 128, BDIM);
        gemm_h<8><<<grid, 128, GEMM_SMEM>>>(uTh, p, out, LDIM, LDIM, LDIM, LDIM,
            CL, LL, CL, b2, 0.f, x, rsum, nullptr, nullptr, nullptr);
    }
}

// round 17
// speedup vs baseline: 1.0526x; 1.0192x over previous
#include <cuda_runtime.h>
#include <cuda_fp16.h>
#include <cstdint>

// Problem: x [B=8, C=512, L=2048], GroupNorm(32) -> QKV -> attention -> O-proj + residual.
// Algebra: out = Pn @ (h @ (Wo·Wv)^T) + (Wo·bv + bo) + x   (softmax rows sum to 1)
#define BDIM 8
#define CDIM 512
#define LDIM 2048
#define NGRP 32
#define CPG  (CDIM / NGRP)   // 16
#define GN_EPS 1e-5f
#define EXP_SHIFT 4.0f

#define CL 1048576LL   // C*L per-batch elems
#define LL 4194304LL   // L*L per-batch elems

// Scratch (bytes):
//  ht   [B,L,C] fp16 @ 0
//  qh   [B,L,C] fp16 @ 16777216
//  kh   [B,L,C] fp16 @ 33554432
//  uTh  [B,C,L] fp16 @ 50331648
//  rsum [B,L]  fp32 @ 67108864
//  b2   [C]    fp32 @ 67174400
//  p    [B,L,L] fp16 @ 83886080
//  wh   [3C,C] fp16 @ 150994944      (wq | wk | W2)
//  wvT  [C,C]  fp16 @ 152567808
//  wo_h [C,C]  fp16 @ 153092096
__device__ __align__(256) unsigned char g_scratch[153616384];

// ---------------------------------------------------------------------------
__device__ __forceinline__ float warp_sum(float v) {
#pragma unroll
    for (int o = 16; o > 0; o >>= 1) v += __shfl_xor_sync(0xFFFFFFFFu, v, o);
    return v;
}
__device__ __forceinline__ void mma_f16(float* c, const uint32_t* a, const uint32_t* b) {
    asm volatile(
        "mma.sync.aligned.m16n8k16.row.col.f32.f16.f16.f32 "
        "{%0,%1,%2,%3}, {%4,%5,%6,%7}, {%8,%9}, {%0,%1,%2,%3};"
        : "+f"(c[0]), "+f"(c[1]), "+f"(c[2]), "+f"(c[3])
        : "r"(a[0]), "r"(a[1]), "r"(a[2]), "r"(a[3]), "r"(b[0]), "r"(b[1]));
}
__device__ __forceinline__ void ldsm_x4(uint32_t& r0, uint32_t& r1, uint32_t& r2,
                                        uint32_t& r3, uint32_t addr) {
    asm volatile("ldmatrix.sync.aligned.m8n8.x4.shared.b16 {%0,%1,%2,%3}, [%4];"
                 : "=r"(r0), "=r"(r1), "=r"(r2), "=r"(r3) : "r"(addr));
}
__device__ __forceinline__ void cp_async16(uint32_t dst, const void* src) {
    asm volatile("cp.async.cg.shared.global [%0], [%1], 16;" :: "r"(dst), "l"(src));
}
__device__ __forceinline__ void cp_commit() {
    asm volatile("cp.async.commit_group;" ::: "memory");
}
template<int N>
__device__ __forceinline__ void cp_wait() {
    asm volatile("cp.async.wait_group %0;" :: "n"(N) : "memory");
}

// ============================================================================
// Weight convert + b2 (one launch):
//  blocks [0,4096)    : wq->wh0, wk->wh1, wv->wvT (transposed), wo->wo_h; rsum=0
//  blocks [4096,4160) : b2[o] = wo[o,:]·bv + bo[o]
// ============================================================================
__global__ __launch_bounds__(256)
void conv_w_kernel(const float* __restrict__ wq, const float* __restrict__ wk,
                   const float* __restrict__ wv, const float* __restrict__ wo,
                   __half* __restrict__ wh, __half* __restrict__ wvT,
                   __half* __restrict__ wo_h, float* __restrict__ rsum,
                   const float* __restrict__ bv, const float* __restrict__ bo,
                   float* __restrict__ b2) {
    if (blockIdx.x < 4096) {
        int i = blockIdx.x * 256 + threadIdx.x;        // 0 .. 4*262144-1
        int which = i >> 18;
        int off = i & 0x3FFFF;
        if (which == 0) {
            wh[off] = __float2half(wq[off]);
        } else if (which == 1) {
            wh[262144 + off] = __float2half(wk[off]);
        } else if (which == 2) {
            // wv[c, e] -> wvT[e, c]
            int c = off >> 9, e = off & 511;
            wvT[e * 512 + c] = __float2half(wv[off]);
        } else {
            wo_h[off] = __float2half(wo[off]);
        }
        if (i < BDIM * LDIM) rsum[i] = 0.f;
    } else {
        const int o = (blockIdx.x - 4096) * 8 + (threadIdx.x >> 5);
        const int lane = threadIdx.x & 31;
        float s = 0.f;
        for (int c = lane; c < CDIM; c += 32) s += wo[o * CDIM + c] * bv[c];
        s = warp_sum(s);
        if (lane == 0) b2[o] = s + bo[o];
    }
}

// ============================================================================
// GroupNorm fused with transpose: x [B,C,L] fp32 -> ht [B,L,C] fp16
// ============================================================================
__global__ __launch_bounds__(256)
void gn_t_kernel(const float* __restrict__ x, const float* __restrict__ gamma,
                 const float* __restrict__ beta, __half* __restrict__ ht) {
    const int b = blockIdx.x / NGRP;
    const int g = blockIdx.x % NGRP;
    const size_t base = ((size_t)b * CDIM + (size_t)g * CPG) * LDIM;
    const float4* xp = reinterpret_cast<const float4*>(x + base);

    const int n4 = CPG * LDIM / 4;  // 8192
    float s = 0.f, ss = 0.f;
    for (int i = threadIdx.x; i < n4; i += 256) {
        float4 t = xp[i];
        s  += t.x + t.y + t.z + t.w;
        ss += t.x * t.x + t.y * t.y + t.z * t.z + t.w * t.w;
    }
    __shared__ float sh1[8], sh2[8];
    __shared__ float scg[CPG], sbg[CPG];
    int lane = threadIdx.x & 31, wid = threadIdx.x >> 5;
    s = warp_sum(s); ss = warp_sum(ss);
    if (lane == 0) { sh1[wid] = s; sh2[wid] = ss; }
    __syncthreads();
    if (wid == 0) {
        s  = (lane < 8) ? sh1[lane] : 0.f;
        ss = (lane < 8) ? sh2[lane] : 0.f;
        s = warp_sum(s); ss = warp_sum(ss);
        if (lane == 0) { sh1[0] = s; sh2[0] = ss; }
    }
    __syncthreads();
    const float inv_n = 1.f / (float)(CPG * LDIM);
    const float mean = sh1[0] * inv_n;
    const float var  = sh2[0] * inv_n - mean * mean;
    const float rstd = rsqrtf(var + GN_EPS);
    if (threadIdx.x < CPG) {
        float sc = gamma[g * CPG + threadIdx.x] * rstd;
        scg[threadIdx.x] = sc;
        sbg[threadIdx.x] = beta[g * CPG + threadIdx.x] - mean * sc;
    }
    __syncthreads();

    __shared__ float tile[CPG][133];
    for (int l0 = 0; l0 < LDIM; l0 += 128) {
        for (int it = threadIdx.x; it < 512; it += 256) {
            int c  = it >> 5;
            int l4 = (it & 31) * 4;
            float4 t = *reinterpret_cast<const float4*>(&x[base + (size_t)c * LDIM + l0 + l4]);
            float sc = scg[c], sb = sbg[c];
            tile[c][l4 + 0] = t.x * sc + sb;
            tile[c][l4 + 1] = t.y * sc + sb;
            tile[c][l4 + 2] = t.z * sc + sb;
            tile[c][l4 + 3] = t.w * sc + sb;
        }
        __syncthreads();
        for (int it = threadIdx.x; it < 512; it += 256) {
            int l  = it >> 2;
            int c4 = (it & 3) * 4;
            __half2* dst = reinterpret_cast<__half2*>(
                ht + ((size_t)b * LDIM + l0 + l) * CDIM + g * CPG + c4);
            dst[0] = __floats2half2_rn(tile[c4 + 0][l], tile[c4 + 1][l]);
            dst[1] = __floats2half2_rn(tile[c4 + 2][l], tile[c4 + 3][l]);
        }
        __syncthreads();
    }
}

// ============================================================================
// fp16 tensor-core GEMM: D[m,n] = sum_k A[m,k]*B[n,k]  (A:[M,K], B:[N,K] fp16)
// CTA: 128 thr (4 warps), 128x128 tile, warp tile 64x64 (2x2 warp grid).
// K-chunk 64 halves, 3-stage cp.async, XOR swizzle, ldmatrix fragment loads,
// register double-buffered fragments. (R11 measured-best configuration.)
// EPI: 0 = fp16 out
//      5 = merged QKU routing (q/k row-major + bias, u transposed no bias)
//      6 = scores: P = fp16(exp(c*alpha - EXP_SHIFT)), atomic row sums -> rsum
//      8 = final: fp32 out = c/rsum[n] + bias[m] + resid[m*ldc+n]
// ============================================================================
#define STAGE_BYTES 32768
#define GEMM_SMEM   (3 * STAGE_BYTES)

template<int EPI>
__global__ __launch_bounds__(128, 2)
void gemm_h(const __half* __restrict__ A, const __half* __restrict__ B,
            void* __restrict__ Dv, int K, int lda, int ldb, int ldc,
            long long sA, long long sB, long long sD,
            const float* __restrict__ bias, float alpha,
            const float* __restrict__ resid, float* __restrict__ rsum,
            void* __restrict__ Dv2, void* __restrict__ Dv3,
            const float* __restrict__ bias2) {
    extern __shared__ char smem[];
    const uint32_t sb = (uint32_t)__cvta_generic_to_shared(smem);
    const int tid = threadIdx.x;
    const int lane = tid & 31;
    const int warp = tid >> 5;
    const int gid = lane >> 2;
    const int tig = lane & 3;
    const int wm = warp & 1;
    const int wn = warp >> 1;
    const int m0 = blockIdx.y * 128;
    const int n0 = blockIdx.x * 128;
    const int bz = blockIdx.z;

    A += (long long)bz * sA;
    B += (long long)bz * sB;

    const int lm = tid >> 3;
    const int lg = tid & 7;
    const __half* Ap = A + (long long)(m0 + lm) * lda + lg * 8;
    const __half* Bp = B + (long long)(n0 + lm) * ldb + lg * 8;
    const uint32_t sts_off = (uint32_t)(lm * 128 + (((lg ^ lm) & 7) << 4));

    const int r7 = lane & 7;
    const int lhi = lane >> 4;
    const int arow = ((lane >> 3) & 1) * 8 + r7;
    const int bhi = (lane >> 3) & 1;
    const int brow = ((lane >> 4) & 1) * 8 + r7;
    uint32_t aRowOff[4], bRowOff[4];
#pragma unroll
    for (int mt = 0; mt < 4; mt++)
        aRowOff[mt] = (uint32_t)((wm * 64 + mt * 16 + arow) * 128);
#pragma unroll
    for (int j = 0; j < 4; j++)
        bRowOff[j] = (uint32_t)((wn * 64 + j * 16 + brow) * 128) + 16384u;

    const int nch = K / 64;

#define ISSUE_STAGE(st, buf) do {                                             \
        const uint32_t d0 = sb + (uint32_t)(buf) * STAGE_BYTES + sts_off;     \
        const __half* ap = Ap + (st) * 64;                                    \
        const __half* bp = Bp + (st) * 64;                                    \
        _Pragma("unroll")                                                     \
        for (int u = 0; u < 8; u++)                                           \
            cp_async16(d0 + u * 2048, ap + (long long)u * 16 * lda);          \
        _Pragma("unroll")                                                     \
        for (int u = 0; u < 8; u++)                                           \
            cp_async16(d0 + 16384 + u * 2048, bp + (long long)u * 16 * ldb);  \
    } while (0)

#define LOAD_FRAGS(sl, ks_) do {                                              \
        const uint32_t swa = (uint32_t)((((2 * (ks_) + lhi) ^ r7) & 7) << 4); \
        const uint32_t swb = (uint32_t)((((2 * (ks_) + bhi) ^ r7) & 7) << 4); \
        _Pragma("unroll")                                                     \
        for (int mt = 0; mt < 4; mt++)                                        \
            ldsm_x4(afr[sl][mt][0], afr[sl][mt][1], afr[sl][mt][2],           \
                    afr[sl][mt][3], stage + aRowOff[mt] + swa);               \
        _Pragma("unroll")                                                     \
        for (int j = 0; j < 4; j++)                                           \
            ldsm_x4(bfr[sl][2 * j][0], bfr[sl][2 * j][1],                     \
                    bfr[sl][2 * j + 1][0], bfr[sl][2 * j + 1][1],             \
                    stage + bRowOff[j] + swb);                                \
    } while (0)

    ISSUE_STAGE(0, 0); cp_commit();
    ISSUE_STAGE(1, 1); cp_commit();

    float acc[4][8][4];
#pragma unroll
    for (int i = 0; i < 4; i++)
#pragma unroll
        for (int j = 0; j < 8; j++)
#pragma unroll
            for (int r = 0; r < 4; r++) acc[i][j][r] = 0.f;

    uint32_t afr[2][4][4], bfr[2][8][2];

    for (int i = 0; i < nch; i++) {
        cp_wait<1>();
        __syncthreads();
        if (i + 2 < nch) ISSUE_STAGE(i + 2, (i + 2) % 3);
        cp_commit();

        const uint32_t stage = sb + (uint32_t)(i % 3) * STAGE_BYTES;
        LOAD_FRAGS(0, 0);
#pragma unroll
        for (int ks = 0; ks < 4; ks++) {
            if (ks < 3) LOAD_FRAGS((ks + 1) & 1, ks + 1);
            const int cur = ks & 1;
#pragma unroll
            for (int mt = 0; mt < 4; mt++)
#pragma unroll
                for (int nt = 0; nt < 8; nt++)
                    mma_f16(acc[mt][nt], afr[cur][mt], bfr[cur][nt]);
        }
    }
#undef ISSUE_STAGE
#undef LOAD_FRAGS

    // EPI 8: per-column inverse attention row-sums (n indexes the L axis)
    float invn[8][2];
    if (EPI == 8) {
#pragma unroll
        for (int nt = 0; nt < 8; nt++) {
            const int n = n0 + wn * 64 + nt * 8 + tig * 2;
            invn[nt][0] = 1.f / rsum[(long long)bz * LDIM + n];
            invn[nt][1] = 1.f / rsum[(long long)bz * LDIM + n + 1];
        }
    }

    // epilogue
#pragma unroll
    for (int mt = 0; mt < 4; mt++) {
        const int m = m0 + wm * 64 + mt * 16 + gid;
        float rs0 = 0.f, rs1 = 0.f;
#pragma unroll
        for (int nt = 0; nt < 8; nt++) {
            const int n = n0 + wn * 64 + nt * 8 + tig * 2;
            float* c = acc[mt][nt];
            if (EPI == 0) {
                __half* Dh = (__half*)Dv + (long long)bz * sD;
                *reinterpret_cast<__half2*>(Dh + (long long)m * ldc + n) =
                    __floats2half2_rn(c[0], c[1]);
                *reinterpret_cast<__half2*>(Dh + (long long)(m + 8) * ldc + n) =
                    __floats2half2_rn(c[2], c[3]);
            } else if (EPI == 5) {  // merged QKU routing
                const int which = n >> 9;          // 0=q, 1=k, 2=u
                const int nl = n & 511;
                if (which < 2) {
                    __half* Dh = ((which == 0) ? (__half*)Dv : (__half*)Dv2)
                                 + (long long)bz * CL;
                    const float* bb = (which == 0) ? bias : bias2;
                    const float b0v = bb[nl], b1v = bb[nl + 1];
                    *reinterpret_cast<__half2*>(Dh + (long long)m * CDIM + nl) =
                        __floats2half2_rn(c[0] + b0v, c[1] + b1v);
                    *reinterpret_cast<__half2*>(Dh + (long long)(m + 8) * CDIM + nl) =
                        __floats2half2_rn(c[2] + b0v, c[3] + b1v);
                } else {            // u slot: transposed, no bias
                    __half* Dh = (__half*)Dv3 + (long long)bz * CL;
                    Dh[(long long)nl * LDIM + m]           = __float2half(c[0]);
                    Dh[(long long)(nl + 1) * LDIM + m]     = __float2half(c[1]);
                    Dh[(long long)nl * LDIM + m + 8]       = __float2half(c[2]);
                    Dh[(long long)(nl + 1) * LDIM + m + 8] = __float2half(c[3]);
                }
            } else if (EPI == 6) {  // scores -> unnormalized softmax numerator
                __half* Dh = (__half*)Dv + (long long)bz * sD;
                const float e0 = __expf(c[0] * alpha - EXP_SHIFT);
                const float e1 = __expf(c[1] * alpha - EXP_SHIFT);
                const float e2 = __expf(c[2] * alpha - EXP_SHIFT);
                const float e3 = __expf(c[3] * alpha - EXP_SHIFT);
                *reinterpret_cast<__half2*>(Dh + (long long)m * ldc + n) =
                    __floats2half2_rn(e0, e1);
                *reinterpret_cast<__half2*>(Dh + (long long)(m + 8) * ldc + n) =
                    __floats2half2_rn(e2, e3);
                rs0 += e0 + e1;
                rs1 += e2 + e3;
            } else {  // EPI == 8: out = c/rsum[n] + b2[m] + x[m,n]
                float* Df = (float*)Dv + (long long)bz * sD;
                const float* rs = resid + (long long)bz * sD;
                const float bm0 = bias[m], bm1 = bias[m + 8];
                const float2 r0 = *reinterpret_cast<const float2*>(
                    &rs[(long long)m * ldc + n]);
                const float2 r1 = *reinterpret_cast<const float2*>(
                    &rs[(long long)(m + 8) * ldc + n]);
                *reinterpret_cast<float2*>(&Df[(long long)m * ldc + n]) =
                    make_float2(c[0] * invn[nt][0] + bm0 + r0.x,
                                c[1] * invn[nt][1] + bm0 + r0.y);
                *reinterpret_cast<float2*>(&Df[(long long)(m + 8) * ldc + n]) =
                    make_float2(c[2] * invn[nt][0] + bm1 + r1.x,
                                c[3] * invn[nt][1] + bm1 + r1.y);
            }
        }
        if (EPI == 6) {
            rs0 += __shfl_xor_sync(0xFFFFFFFFu, rs0, 1);
            rs0 += __shfl_xor_sync(0xFFFFFFFFu, rs0, 2);
            rs1 += __shfl_xor_sync(0xFFFFFFFFu, rs1, 1);
            rs1 += __shfl_xor_sync(0xFFFFFFFFu, rs1, 2);
            if (tig == 0) {
                atomicAdd(&rsum[(long long)bz * LDIM + m], rs0);
                atomicAdd(&rsum[(long long)bz * LDIM + m + 8], rs1);
            }
        }
    }
}

// ============================================================================
// Launch
// ============================================================================
extern "C" void kernel_launch(void* const* d_in, const int* in_sizes, int n_in,
                              void* d_out, int out_size) {
    (void)in_sizes; (void)n_in; (void)out_size;
    const float* x   = (const float*)d_in[0];
    const float* gns = (const float*)d_in[1];
    const float* gnb = (const float*)d_in[2];
    const float* wq  = (const float*)d_in[3];
    const float* bq  = (const float*)d_in[4];
    const float* wk  = (const float*)d_in[5];
    const float* bk  = (const float*)d_in[6];
    const float* wv  = (const float*)d_in[7];
    const float* bv  = (const float*)d_in[8];
    const float* wo  = (const float*)d_in[9];
    const float* bo  = (const float*)d_in[10];
    float* out = (float*)d_out;

    unsigned char* base = nullptr;
    cudaGetSymbolAddress((void**)&base, g_scratch);
    __half* ht   = (__half*)(base);
    __half* qh   = (__half*)(base + 16777216);
    __half* kh   = (__half*)(base + 33554432);
    __half* uTh  = (__half*)(base + 50331648);
    float*  rsum = (float*)(base + 67108864);
    float*  b2   = (float*)(base + 67174400);
    __half* p    = (__half*)(base + 83886080);
    __half* wh   = (__half*)(base + 150994944);   // [wq | wk | W2]
    __half* wvT  = (__half*)(base + 152567808);
    __half* woh  = (__half*)(base + 153092096);
    __half* w2h  = wh + 524288;                   // slot 2 of wh

    const float attn_scale = 0.044194173824159216f;  // 512^-0.5

    static bool attr_done = false;
    if (!attr_done) {
        cudaFuncSetAttribute(gemm_h<0>, cudaFuncAttributeMaxDynamicSharedMemorySize, GEMM_SMEM);
        cudaFuncSetAttribute(gemm_h<5>, cudaFuncAttributeMaxDynamicSharedMemorySize, GEMM_SMEM);
        cudaFuncSetAttribute(gemm_h<6>, cudaFuncAttributeMaxDynamicSharedMemorySize, GEMM_SMEM);
        cudaFuncSetAttribute(gemm_h<8>, cudaFuncAttributeMaxDynamicSharedMemorySize, GEMM_SMEM);
        attr_done = true;
    }

    // 0) Weights -> fp16 (wq, wk, wvT, wo), zero rsum, b2 = Wo@bv + bo (one launch)
    conv_w_kernel<<<4160, 256>>>(wq, wk, wv, wo, wh, wvT, woh, rsum, bv, bo, b2);

    // 1) W2 = Wo @ Wv  (fp16, 512x512x512): D[o,e] = sum_c woh[o,c]*wvT[e,c]
    {
        dim3 grid(4, 4, 1);
        gemm_h<0><<<grid, 128, GEMM_SMEM>>>(woh, wvT, w2h, CDIM, CDIM, CDIM, CDIM,
            0, 0, 0, nullptr, 0.f, nullptr, nullptr, nullptr, nullptr, nullptr);
    }

    // 2) GroupNorm + transpose: ht [B, L, C] fp16
    gn_t_kernel<<<BDIM * NGRP, 256>>>(x, gns, gnb, ht);

    // 3) Merged QKU projection: M=L, N=3C=1536, K=C
    {
        dim3 grid(1536 / 128, LDIM / 128, BDIM);
        gemm_h<5><<<grid, 128, GEMM_SMEM>>>(ht, wh, qh, CDIM, CDIM, CDIM, CDIM,
            CL, 0, CL, bq, 0.f, nullptr, nullptr, kh, uTh, bk);
    }

    // 4) Scores fused with exp: p[i,j] = fp16(exp(scale*q.k - 4)), rsum[i] += ...
    {
        dim3 grid(LDIM / 128, LDIM / 128, BDIM);
        gemm_h<6><<<grid, 128, GEMM_SMEM>>>(qh, kh, p, CDIM, CDIM, CDIM, LDIM,
            CL, CL, LL, nullptr, attn_scale, nullptr, rsum, nullptr, nullptr,
            nullptr);
    }

    // 5) Final: out[o,l] = sum_j p[l,j]*uT[o,j] / rsum[l] + b2[o] + x[o,l]
    {
        dim3 grid(LDIM / 128, CDIM / 128, BDIM);
        gemm_h<8><<<grid, 128, GEMM_SMEM>>>(uTh, p, out, LDIM, LDIM, LDIM, LDIM,
            CL, LL, CL, b2, 0.f, x, rsum, nullptr, nullptr, nullptr);
    }
}